// round 5
// baseline (speedup 1.0000x reference)
#include <cuda_runtime.h>
#include <math.h>

#define TT    2048
#define BATCH 16
#define HD    512
#define G4    2048
#define NCTA  128
#define NTH   256
#define ROWS  16
#define HU    4
#define BH    (BATCH * HD)

typedef unsigned long long u64;

__device__ __forceinline__ u64 fma2(u64 a, u64 b, u64 c) {
    u64 d;
    asm("fma.rn.f32x2 %0, %1, %2, %3;" : "=l"(d) : "l"(a), "l"(b), "l"(c));
    return d;
}
__device__ __forceinline__ u64 pk2(float a, float b) {
    u64 d;
    asm("mov.b64 %0, {%1, %2};" : "=l"(d) : "f"(a), "f"(b));
    return d;
}
__device__ __forceinline__ float lo_f(u64 v) { return __uint_as_float((unsigned)v); }
__device__ __forceinline__ float hi_f(u64 v) { return __uint_as_float((unsigned)(v >> 32)); }

// Scratch (__device__ globals per allocation-free rules)
__device__ float g_x0[(size_t)TT * NCTA * 256];   // [t][cta][b][16 local rows]
__device__ float g_h0[2][BH];
__device__ float g_h1[2][BH];
__device__ unsigned g_ctr[64];                    // [0]=A (h0), [32]=B (h1)

__device__ __forceinline__ void cta_arrive(unsigned* p) {
    asm volatile("red.release.gpu.add.u32 [%0], %1;" :: "l"(p), "r"(1u) : "memory");
}
__device__ __forceinline__ void cta_spin(unsigned* p, unsigned tgt) {
    unsigned v;
    do {
        asm volatile("ld.acquire.gpu.u32 %0, [%1];" : "=r"(v) : "l"(p) : "memory");
    } while (v < tgt);
}
__device__ __forceinline__ void named_bar(int id, int cnt) {
    asm volatile("bar.sync %0, %1;" :: "r"(id), "r"(cnt) : "memory");
}

// ---------------------------------------------------------------------------
// X0 GEMM (+ scratch init in block (0,0)): packed-j f32x2 FMAs.
// ---------------------------------------------------------------------------
__global__ void __launch_bounds__(256) x0_gemm_kernel(
    const float* __restrict__ A, const float* __restrict__ W,
    const float* __restrict__ bias)
{
    // Reset counters + zero the phantom h buffers each call (runs before slstm
    // in stream order; previous slstm has completed).
    if (blockIdx.x == 0 && blockIdx.y == 0) {
        for (int i = threadIdx.x; i < 64; i += 256) g_ctr[i] = 0u;
        for (int i = threadIdx.x; i < BH; i += 256) {
            g_h0[0][i] = 0.f; g_h0[1][i] = 0.f;
            g_h1[0][i] = 0.f; g_h1[1][i] = 0.f;
        }
    }

    __shared__ float As[16][68];
    __shared__ float Ws[16][68];
    int tid = threadIdx.x;
    int tx = tid & 15, ty = tid >> 4;
    int m0 = blockIdx.y * 64, n0 = blockIdx.x * 64;
    int lr = tid >> 2;
    int lc = (tid & 3) << 2;
    u64 acc2[4][2] = {};
    for (int k0 = 0; k0 < 512; k0 += 16) {
        float4 av = *(const float4*)&A[(size_t)(m0 + lr) * 512 + k0 + lc];
        float4 wv = *(const float4*)&W[(size_t)(n0 + lr) * 512 + k0 + lc];
        As[lc + 0][lr] = av.x; As[lc + 1][lr] = av.y;
        As[lc + 2][lr] = av.z; As[lc + 3][lr] = av.w;
        Ws[lc + 0][lr] = wv.x; Ws[lc + 1][lr] = wv.y;
        Ws[lc + 2][lr] = wv.z; Ws[lc + 3][lr] = wv.w;
        __syncthreads();
        #pragma unroll
        for (int k = 0; k < 16; ++k) {
            float4 a4 = *(const float4*)&As[k][ty * 4];
            ulonglong2 w2 = *(const ulonglong2*)&Ws[k][tx * 4];
            u64 pa0 = pk2(a4.x, a4.x);
            u64 pa1 = pk2(a4.y, a4.y);
            u64 pa2 = pk2(a4.z, a4.z);
            u64 pa3 = pk2(a4.w, a4.w);
            acc2[0][0] = fma2(pa0, w2.x, acc2[0][0]);
            acc2[0][1] = fma2(pa0, w2.y, acc2[0][1]);
            acc2[1][0] = fma2(pa1, w2.x, acc2[1][0]);
            acc2[1][1] = fma2(pa1, w2.y, acc2[1][1]);
            acc2[2][0] = fma2(pa2, w2.x, acc2[2][0]);
            acc2[2][1] = fma2(pa2, w2.y, acc2[2][1]);
            acc2[3][0] = fma2(pa3, w2.x, acc2[3][0]);
            acc2[3][1] = fma2(pa3, w2.y, acc2[3][1]);
        }
        __syncthreads();
    }
    float4 bv = *(const float4*)&bias[n0 + tx * 4];
    int n = n0 + tx * 4;
    int g = n >> 9;
    int cta = (n >> 2) & 127;
    #pragma unroll
    for (int i = 0; i < 4; ++i) {
        int m = m0 + ty * 4 + i;
        int t = m >> 4, b = m & 15;
        float4 r;
        r.x = lo_f(acc2[i][0]) + bv.x; r.y = hi_f(acc2[i][0]) + bv.y;
        r.z = lo_f(acc2[i][1]) + bv.z; r.w = hi_f(acc2[i][1]) + bv.w;
        size_t dst = (((size_t)t * NCTA + cta) * 16 + b) * 16 + g * 4;
        *(float4*)&g_x0[dst] = r;
    }
}

// ---------------------------------------------------------------------------
// Persistent recurrent kernel: two decoupled warp groups, no __syncthreads
// in the loop. WG0 (warps 0-3) = layer 0 step t; WG1 (warps 4-7) = layer 1
// step t-1. Per-warp private h slices loaded straight from L2.
// ---------------------------------------------------------------------------
__global__ void __launch_bounds__(NTH, 1) slstm_kernel(
    const float* __restrict__ w_hh0,
    const float* __restrict__ w_ih1,
    const float* __restrict__ w_hh1,
    const float* __restrict__ b1,
    float* __restrict__ out)
{
    extern __shared__ float sm[];
    float* w0s  = sm;                  // 8192
    float* w1is = sm + 8192;           // 8192
    float* w1hs = sm + 16384;          // 8192
    float* sh0  = sm + 24576;          // 4 warps x 16 x 33 f4 = 8448 floats
    float* sh0x = sm + 33024;          // 8448
    float* sh1  = sm + 41472;          // 8448
    float* pb0  = sm + 49920;          // 1056
    float* pb1  = sm + 50976;          // 1056
    float* gb0  = sm + 52032;          // 272
    float* gb1  = sm + 52304;          // 272
    float* c0s  = sm + 52576;          // 64 each
    float* n0s  = sm + 52640;
    float* c1s  = sm + 52704;
    float* n1s  = sm + 52768;
    float* hf0  = sm + 52832;
    float* hf1  = sm + 52896;
    float* b1s  = sm + 52960;          // 16

    const int cta  = blockIdx.x;
    const int tid  = threadIdx.x;
    const int w    = tid >> 5;
    const int lane = tid & 31;
    const int r2   = lane >> 2;
    const int bq   = lane & 3;
    const bool is0 = (w < 4);
    const int kw   = w & 3;            // k-chunk id within group
    const int gt   = tid & 127;        // id within group

    float4* w0f  = (float4*)w0s;
    float4* w1if = (float4*)w1is;
    float4* w1hf = (float4*)w1hs;
    float4* myh0  = (float4*)(sh0  + kw * 2112);   // 16 x 33 f4
    float4* myh0x = (float4*)(sh0x + kw * 2112);
    float4* myh1  = (float4*)(sh1  + kw * 2112);

    // Load weight slices, permuted: f4 (row,c) -> c*16 + (row&1)*8 + (row>>1)
    #pragma unroll
    for (int i = 0; i < 8; ++i) {
        int idx = tid + i * NTH;
        int r = idx >> 7;
        int c = idx & 127;
        int grow = (r >> 2) * HD + cta * HU + (r & 3);
        int dst = c * 16 + (r & 1) * 8 + (r >> 1);
        w0f[dst]  = ((const float4*)(w_hh0 + (size_t)grow * 512))[c];
        w1if[dst] = ((const float4*)(w_ih1 + (size_t)grow * 512))[c];
        w1hf[dst] = ((const float4*)(w_hh1 + (size_t)grow * 512))[c];
    }
    if (tid < ROWS) {
        int grow = (tid >> 2) * HD + cta * HU + (tid & 3);
        b1s[tid] = b1[grow];
    }
    if (tid < 64) { c0s[tid] = 0.f; n0s[tid] = 0.f; c1s[tid] = 0.f; n1s[tid] = 0.f; }
    __syncthreads();

    const ulonglong2* W0  = (const ulonglong2*)w0s;
    const ulonglong2* W1I = (const ulonglong2*)w1is;
    const ulonglong2* W1H = (const ulonglong2*)w1hs;

    const int cb = gt >> 2, cu = gt & 3;          // cell mapping (gt<64)
    const int hidx = cb * HD + cta * HU + cu;
    const float biasr = b1s[gt & 15];
    unsigned* ctrA = &g_ctr[0];
    unsigned* ctrB = &g_ctr[32];

    for (int t = 0; t <= TT; ++t) {
        if (is0) {
            if (t < TT) {
                // x0 prefetch before spin (independent, hides DRAM latency)
                size_t xbase = ((size_t)t * NCTA + cta) * 256;
                float x0a = __ldcg(&g_x0[xbase + gt]);
                float x0b = __ldcg(&g_x0[xbase + gt + 128]);

                // gate: h0(t-1) published by all; h1(t-2) published (WAR guard)
                if (lane == 0) {
                    if (t > 0) cta_spin(ctrA, 128u * (unsigned)t);
                    if (t > 1) cta_spin(ctrB, 128u * (unsigned)(t - 1));
                }
                __syncwarp();

                // load own k-slice of h0(t-1)
                {
                    const float4* src = (const float4*)g_h0[(t + 1) & 1];
                    #pragma unroll
                    for (int b8 = 0; b8 < 16; ++b8)
                        myh0[b8 * 33 + lane] = __ldcg(src + b8 * 128 + kw * 32 + lane);
                }
                __syncwarp();

                // L0 GEMM over own 32-f4 k-chunk
                u64 p0[4] = {0ull, 0ull, 0ull, 0ull};
                u64 p1[4] = {0ull, 0ull, 0ull, 0ull};
                #pragma unroll 8
                for (int kv = 0; kv < 32; ++kv) {
                    int k4 = (kw << 5) + kv;
                    ulonglong2 wa = W0[k4 * 16 + r2];
                    ulonglong2 wb = W0[k4 * 16 + 8 + r2];
                    #pragma unroll
                    for (int m = 0; m < 4; ++m) {
                        ulonglong2 h = *(const ulonglong2*)(myh0 + (bq + 4 * m) * 33 + kv);
                        p0[m] = fma2(wa.x, h.x, p0[m]);
                        p0[m] = fma2(wa.y, h.y, p0[m]);
                        p1[m] = fma2(wb.x, h.x, p1[m]);
                        p1[m] = fma2(wb.y, h.y, p1[m]);
                    }
                }
                #pragma unroll
                for (int m = 0; m < 4; ++m) {
                    pb0[kw * 264 + (bq + 4 * m) * 16 + 2 * r2]     = lo_f(p0[m]) + hi_f(p0[m]);
                    pb0[kw * 264 + (bq + 4 * m) * 16 + 2 * r2 + 1] = lo_f(p1[m]) + hi_f(p1[m]);
                }
                named_bar(2, 128);

                // reduce (2 outputs per thread)
                {
                    float ga = x0a + pb0[gt] + pb0[264 + gt] + pb0[528 + gt] + pb0[792 + gt];
                    int o2 = gt + 128;
                    float gbv = x0b + pb0[o2] + pb0[264 + o2] + pb0[528 + o2] + pb0[792 + o2];
                    gb0[(gt >> 4) * 17 + (gt & 15)] = ga;
                    gb0[(o2 >> 4) * 17 + (o2 & 15)] = gbv;
                }
                named_bar(2, 128);

                // cell0 (warps 0-1) + publish
                if (gt < 64) {
                    float gi = gb0[cb * 17 + 0  + cu];
                    float gf = gb0[cb * 17 + 4  + cu];
                    float gg = gb0[cb * 17 + 8  + cu];
                    float go = gb0[cb * 17 + 12 + cu];
                    float iv = expf(gi);
                    float fv = 1.f / (1.f + expf(-gf));
                    float gv = tanhf(gg);
                    float ov = 1.f / (1.f + expf(-go));
                    float nv = fmaf(fv, n0s[gt], iv);
                    float cv = fmaf(fv, c0s[gt], iv * gv);
                    float hv = ov * (cv / (nv + 1e-8f));
                    n0s[gt] = nv; c0s[gt] = cv; hf0[gt] = hv;
                    g_h0[t & 1][hidx] = hv;
                    named_bar(4, 64);
                    if (gt == 0) cta_arrive(ctrA);
                }
            }
        } else {
            if (t >= 1) {
                int s = t - 1;
                // gate: h0(t-1) and h1(t-2) published by all
                if (lane == 0) {
                    cta_spin(ctrA, 128u * (unsigned)t);
                    if (t > 1) cta_spin(ctrB, 128u * (unsigned)(t - 1));
                }
                __syncwarp();

                // load own k-slices of h0(t-1) and h1(t-2)
                {
                    const float4* s0 = (const float4*)g_h0[(t + 1) & 1];
                    const float4* s1 = (const float4*)g_h1[t & 1];
                    #pragma unroll
                    for (int b8 = 0; b8 < 16; ++b8) {
                        myh0x[b8 * 33 + lane] = __ldcg(s0 + b8 * 128 + kw * 32 + lane);
                        myh1 [b8 * 33 + lane] = __ldcg(s1 + b8 * 128 + kw * 32 + lane);
                    }
                }
                __syncwarp();

                // L1 GEMM: W1I@h0(s) + W1H@h1(s-1) over own k-chunk
                u64 q0[4] = {0ull, 0ull, 0ull, 0ull};
                u64 q1[4] = {0ull, 0ull, 0ull, 0ull};
                #pragma unroll 4
                for (int kv = 0; kv < 32; ++kv) {
                    int k4 = (kw << 5) + kv;
                    ulonglong2 wia = W1I[k4 * 16 + r2];
                    ulonglong2 wib = W1I[k4 * 16 + 8 + r2];
                    ulonglong2 wha = W1H[k4 * 16 + r2];
                    ulonglong2 whb = W1H[k4 * 16 + 8 + r2];
                    #pragma unroll
                    for (int m = 0; m < 4; ++m) {
                        ulonglong2 x = *(const ulonglong2*)(myh0x + (bq + 4 * m) * 33 + kv);
                        ulonglong2 h = *(const ulonglong2*)(myh1  + (bq + 4 * m) * 33 + kv);
                        q0[m] = fma2(wia.x, x.x, q0[m]);
                        q0[m] = fma2(wia.y, x.y, q0[m]);
                        q0[m] = fma2(wha.x, h.x, q0[m]);
                        q0[m] = fma2(wha.y, h.y, q0[m]);
                        q1[m] = fma2(wib.x, x.x, q1[m]);
                        q1[m] = fma2(wib.y, x.y, q1[m]);
                        q1[m] = fma2(whb.x, h.x, q1[m]);
                        q1[m] = fma2(whb.y, h.y, q1[m]);
                    }
                }
                #pragma unroll
                for (int m = 0; m < 4; ++m) {
                    pb1[kw * 264 + (bq + 4 * m) * 16 + 2 * r2]     = lo_f(q0[m]) + hi_f(q0[m]);
                    pb1[kw * 264 + (bq + 4 * m) * 16 + 2 * r2 + 1] = lo_f(q1[m]) + hi_f(q1[m]);
                }
                named_bar(3, 128);

                {
                    float ga = biasr + pb1[gt] + pb1[264 + gt] + pb1[528 + gt] + pb1[792 + gt];
                    int o2 = gt + 128;
                    float gbv = biasr + pb1[o2] + pb1[264 + o2] + pb1[528 + o2] + pb1[792 + o2];
                    gb1[(gt >> 4) * 17 + (gt & 15)] = ga;
                    gb1[(o2 >> 4) * 17 + (o2 & 15)] = gbv;
                }
                named_bar(3, 128);

                // cell1 (warps 4-5) + publish + output
                if (gt < 64) {
                    float gi = gb1[cb * 17 + 0  + cu];
                    float gf = gb1[cb * 17 + 4  + cu];
                    float gg = gb1[cb * 17 + 8  + cu];
                    float go = gb1[cb * 17 + 12 + cu];
                    float iv = expf(gi);
                    float fv = 1.f / (1.f + expf(-gf));
                    float gv = tanhf(gg);
                    float ov = 1.f / (1.f + expf(-go));
                    float nv = fmaf(fv, n1s[gt], iv);
                    float cv = fmaf(fv, c1s[gt], iv * gv);
                    float hv = ov * (cv / (nv + 1e-8f));
                    n1s[gt] = nv; c1s[gt] = cv; hf1[gt] = hv;
                    g_h1[s & 1][hidx] = hv;
                    out[(size_t)s * BH + hidx] = hv;
                    named_bar(5, 64);
                    if (gt == 0) cta_arrive(ctrB);
                }
            }
        }
    }

    __syncthreads();
    // Final states after output_seq: hn[2,B,H], cn[2,B,H], nn[2,B,H]
    if (tid < 64) {
        size_t base = (size_t)TT * BH;
        out[base + 0 * BH + hidx] = hf0[tid];
        out[base + 1 * BH + hidx] = hf1[tid];
        out[base + 2 * BH + hidx] = c0s[tid];
        out[base + 3 * BH + hidx] = c1s[tid];
        out[base + 4 * BH + hidx] = n0s[tid];
        out[base + 5 * BH + hidx] = n1s[tid];
    }
}

extern "C" void kernel_launch(void* const* d_in, const int* in_sizes, int n_in,
                              void* d_out, int out_size) {
    (void)in_sizes; (void)n_in; (void)out_size;
    const float* input  = (const float*)d_in[0];
    const float* w_ih0  = (const float*)d_in[1];
    const float* w_hh0  = (const float*)d_in[2];
    const float* b0     = (const float*)d_in[3];
    const float* w_ih1  = (const float*)d_in[4];
    const float* w_hh1  = (const float*)d_in[5];
    const float* b1     = (const float*)d_in[6];
    float* out = (float*)d_out;

    int smem_bytes = 52976 * 4;   // 211904 B
    cudaFuncSetAttribute(slstm_kernel, cudaFuncAttributeMaxDynamicSharedMemorySize, smem_bytes);

    x0_gemm_kernel<<<dim3(G4 / 64, (TT * BATCH) / 64), 256>>>(input, w_ih0, b0);
    slstm_kernel<<<NCTA, NTH, smem_bytes>>>(w_hh0, w_ih1, w_hh1, b1, out);
}

// round 6
// speedup vs baseline: 1.1263x; 1.1263x over previous
#include <cuda_runtime.h>
#include <math.h>

#define TT    2048
#define BATCH 16
#define HD    512
#define G4    2048
#define NCTA  128
#define NTH   256
#define BH    (BATCH * HD)

typedef unsigned long long u64;

__device__ __forceinline__ u64 fma2(u64 a, u64 b, u64 c) {
    u64 d;
    asm("fma.rn.f32x2 %0, %1, %2, %3;" : "=l"(d) : "l"(a), "l"(b), "l"(c));
    return d;
}
__device__ __forceinline__ u64 pk2(float a, float b) {
    u64 d;
    asm("mov.b64 %0, {%1, %2};" : "=l"(d) : "f"(a), "f"(b));
    return d;
}
__device__ __forceinline__ float lo_f(u64 v) { return __uint_as_float((unsigned)v); }
__device__ __forceinline__ float hi_f(u64 v) { return __uint_as_float((unsigned)(v >> 32)); }

// Scratch (__device__ globals per allocation-free rules)
__device__ float g_x0[(size_t)TT * NCTA * 256];   // [t][cta][b][16 rows]
__device__ float g_h0[2][BH];
__device__ float g_h1[2][BH];
__device__ unsigned g_ctr[32];

__device__ __forceinline__ void cta_arrive(unsigned* p) {
    asm volatile("red.release.gpu.add.u32 [%0], %1;" :: "l"(p), "r"(1u) : "memory");
}
__device__ __forceinline__ void cta_spin(unsigned* p, unsigned tgt) {
    unsigned v;
    do {
        asm volatile("ld.acquire.gpu.u32 %0, [%1];" : "=r"(v) : "l"(p) : "memory");
    } while (v < tgt);
}

// ---------------------------------------------------------------------------
// X0 GEMM (+ scratch init in block (0,0)): packed-j f32x2 FMAs.
// ---------------------------------------------------------------------------
__global__ void __launch_bounds__(256) x0_gemm_kernel(
    const float* __restrict__ A, const float* __restrict__ W,
    const float* __restrict__ bias)
{
    if (blockIdx.x == 0 && blockIdx.y == 0) {
        for (int i = threadIdx.x; i < 32; i += 256) g_ctr[i] = 0u;
        for (int i = threadIdx.x; i < BH; i += 256) {
            g_h0[0][i] = 0.f; g_h0[1][i] = 0.f;
            g_h1[0][i] = 0.f; g_h1[1][i] = 0.f;
        }
    }

    __shared__ float As[16][68];
    __shared__ float Ws[16][68];
    int tid = threadIdx.x;
    int tx = tid & 15, ty = tid >> 4;
    int m0 = blockIdx.y * 64, n0 = blockIdx.x * 64;
    int lr = tid >> 2;
    int lc = (tid & 3) << 2;
    u64 acc2[4][2] = {};
    for (int k0 = 0; k0 < 512; k0 += 16) {
        float4 av = *(const float4*)&A[(size_t)(m0 + lr) * 512 + k0 + lc];
        float4 wv = *(const float4*)&W[(size_t)(n0 + lr) * 512 + k0 + lc];
        As[lc + 0][lr] = av.x; As[lc + 1][lr] = av.y;
        As[lc + 2][lr] = av.z; As[lc + 3][lr] = av.w;
        Ws[lc + 0][lr] = wv.x; Ws[lc + 1][lr] = wv.y;
        Ws[lc + 2][lr] = wv.z; Ws[lc + 3][lr] = wv.w;
        __syncthreads();
        #pragma unroll
        for (int k = 0; k < 16; ++k) {
            float4 a4 = *(const float4*)&As[k][ty * 4];
            ulonglong2 w2 = *(const ulonglong2*)&Ws[k][tx * 4];
            u64 pa0 = pk2(a4.x, a4.x);
            u64 pa1 = pk2(a4.y, a4.y);
            u64 pa2 = pk2(a4.z, a4.z);
            u64 pa3 = pk2(a4.w, a4.w);
            acc2[0][0] = fma2(pa0, w2.x, acc2[0][0]);
            acc2[0][1] = fma2(pa0, w2.y, acc2[0][1]);
            acc2[1][0] = fma2(pa1, w2.x, acc2[1][0]);
            acc2[1][1] = fma2(pa1, w2.y, acc2[1][1]);
            acc2[2][0] = fma2(pa2, w2.x, acc2[2][0]);
            acc2[2][1] = fma2(pa2, w2.y, acc2[2][1]);
            acc2[3][0] = fma2(pa3, w2.x, acc2[3][0]);
            acc2[3][1] = fma2(pa3, w2.y, acc2[3][1]);
        }
        __syncthreads();
    }
    float4 bv = *(const float4*)&bias[n0 + tx * 4];
    int n = n0 + tx * 4;
    int g = n >> 9;
    int cta = (n >> 2) & 127;
    #pragma unroll
    for (int i = 0; i < 4; ++i) {
        int m = m0 + ty * 4 + i;
        int t = m >> 4, b = m & 15;
        float4 r;
        r.x = lo_f(acc2[i][0]) + bv.x; r.y = hi_f(acc2[i][0]) + bv.y;
        r.z = lo_f(acc2[i][1]) + bv.z; r.w = hi_f(acc2[i][1]) + bv.w;
        size_t dst = (((size_t)t * NCTA + cta) * 16 + b) * 16 + g * 4;
        *(float4*)&g_x0[dst] = r;
    }
}

// ---------------------------------------------------------------------------
// Persistent recurrent kernel: fused L0(t)+L1(t-1) GEMM, 4x4x8 register tile,
// conflict-free swizzled smem, shuffle-based cells with register state.
// ---------------------------------------------------------------------------
// smem float offsets
#define SM_W0   0
#define SM_W1I  8192
#define SM_W1H  16384
#define SM_H0   24576
#define SM_H1   32768
#define SM_PB0  40960
#define SM_PB1  45312
#define SM_TOT  49664

__global__ void __launch_bounds__(NTH, 1) slstm_kernel(
    const float* __restrict__ w_hh0,
    const float* __restrict__ w_ih1,
    const float* __restrict__ w_hh1,
    const float* __restrict__ b1,
    float* __restrict__ out)
{
    extern __shared__ float sm[];
    const ulonglong2* W0u  = (const ulonglong2*)(sm + SM_W0);
    const ulonglong2* W1Iu = (const ulonglong2*)(sm + SM_W1I);
    const ulonglong2* W1Hu = (const ulonglong2*)(sm + SM_W1H);
    ulonglong2* H0u = (ulonglong2*)(sm + SM_H0);
    ulonglong2* H1u = (ulonglong2*)(sm + SM_H1);
    float* pb0 = sm + SM_PB0;
    float* pb1 = sm + SM_PB1;

    const int cta  = blockIdx.x;
    const int tid  = threadIdx.x;
    const int lane = tid & 31;
    const int wp   = tid >> 5;
    const int bg   = tid & 3;
    const int rg   = (tid >> 2) & 3;
    const int cb2  = (tid >> 4) & 1;
    const int kc   = 2 * wp + cb2;
    const int wsel = 2 * rg + cb2;

    // ---- load weights into swizzled smem (once; conflicts here don't matter)
    // storage: sidx(k4,r) = ((k4>>4)*8 + (k4&7))*32 + 8*(r&3) + 2*(r>>2) + ((k4>>3)&1)
    #pragma unroll
    for (int i = 0; i < 8; ++i) {
        int idx = tid + i * NTH;            // f4 index 0..2047
        int r = idx >> 7;
        int col = idx & 127;
        int grow = (r >> 2) * HD + cta * 4 + (r & 3);
        int sidx = ((col >> 4) * 8 + (col & 7)) * 32
                 + 8 * (r & 3) + 2 * (r >> 2) + ((col >> 3) & 1);
        const ulonglong2* s0 = (const ulonglong2*)(w_hh0 + (size_t)grow * 512);
        const ulonglong2* s1 = (const ulonglong2*)(w_ih1 + (size_t)grow * 512);
        const ulonglong2* s2 = (const ulonglong2*)(w_hh1 + (size_t)grow * 512);
        ((ulonglong2*)(sm + SM_W0))[sidx]  = s0[col];
        ((ulonglong2*)(sm + SM_W1I))[sidx] = s1[col];
        ((ulonglong2*)(sm + SM_W1H))[sidx] = s2[col];
    }
    __syncthreads();

    // reduce-side mapping
    const int rb  = tid >> 4;              // batch for reduce/cell
    const int row = tid & 15;              // gate row for reduce
    float biasr;
    {
        int grow = (row >> 2) * HD + cta * 4 + (row & 3);
        biasr = b1[grow];
    }
    // cell lanes
    const bool isC0 = (row < 4);
    const bool isC1 = (row >= 8 && row < 12);
    const int hidx0 = rb * HD + cta * 4 + row;        // valid when isC0
    const int hidx1 = rb * HD + cta * 4 + (row - 8);  // valid when isC1
    float c0r = 0.f, n0r = 0.f, h0fin = 0.f;
    float c1r = 0.f, n1r = 0.f, h1fin = 0.f;

    unsigned* ctr = &g_ctr[0];
    const int lane16 = lane & 15;
    const int lhi = lane >> 4;

    for (int t = 0; t <= TT; ++t) {
        // x0 prefetch (static data; before spin)
        float x0v = 0.f;
        if (t < TT) x0v = __ldcg(&g_x0[(((size_t)t * NCTA + cta) * 256) + tid]);

        // ---- spin: all CTAs finished slot t-1 (h0(t-1), h1(t-2) published)
        if (t > 0) {
            if (lane == 0) cta_spin(ctr, 128u * (unsigned)t);
            __syncwarp();
        }

        // ---- reload own warp's k-region of h0(t-1), h1(t-2) into swizzled smem
        {
            const float4* s0 = (const float4*)g_h0[(t + 1) & 1];
            const float4* s1 = (const float4*)g_h1[t & 1];
            int k4 = 16 * wp + lane16;
            int kv = lane16 & 7, cc = (lane16 >> 3) & 1;
            #pragma unroll
            for (int i = 0; i < 8; ++i) {
                int b = 2 * i + lhi;
                float4 v0 = __ldcg(s0 + b * 128 + k4);
                float4 v1 = __ldcg(s1 + b * 128 + k4);
                int sidx = (wp * 8 + kv) * 32
                         + ((8 * (b >> 2) + 2 * (b & 3) + cc + kv) & 31);
                ((float4*)(sm + SM_H0))[sidx] = v0;
                ((float4*)(sm + SM_H1))[sidx] = v1;
            }
            __syncwarp();
        }

        // ---- fused GEMM: L0 (W0 @ h0) and L1 (W1I @ h0 + W1H @ h1)
        u64 acc0[16], acc1[16];
        #pragma unroll
        for (int z = 0; z < 16; ++z) { acc0[z] = 0ull; acc1[z] = 0ull; }

        #pragma unroll 4
        for (int kv = 0; kv < 8; ++kv) {
            int blk = (wp * 8 + kv) * 32;
            int hrot = 2 * bg + cb2 + kv;
            ulonglong2 h0v[4], h1v[4];
            #pragma unroll
            for (int j = 0; j < 4; ++j) {
                int off = blk + ((8 * j + hrot) & 31);
                h0v[j] = H0u[off];
                h1v[j] = H1u[off];
            }
            #pragma unroll
            for (int i = 0; i < 4; ++i) {
                int woff = blk + 8 * i + wsel;
                ulonglong2 w0 = W0u[woff];
                ulonglong2 wi = W1Iu[woff];
                ulonglong2 wh = W1Hu[woff];
                #pragma unroll
                for (int j = 0; j < 4; ++j) {
                    acc0[i * 4 + j] = fma2(w0.x, h0v[j].x, acc0[i * 4 + j]);
                    acc0[i * 4 + j] = fma2(w0.y, h0v[j].y, acc0[i * 4 + j]);
                    acc1[i * 4 + j] = fma2(wi.x, h0v[j].x, acc1[i * 4 + j]);
                    acc1[i * 4 + j] = fma2(wi.y, h0v[j].y, acc1[i * 4 + j]);
                    acc1[i * 4 + j] = fma2(wh.x, h1v[j].x, acc1[i * 4 + j]);
                    acc1[i * 4 + j] = fma2(wh.y, h1v[j].y, acc1[i * 4 + j]);
                }
            }
        }

        // ---- store partials (scalar STS, bank-verified conflict-free)
        #pragma unroll
        for (int i = 0; i < 4; ++i) {
            #pragma unroll
            for (int j = 0; j < 4; ++j) {
                int r = 4 * rg + i, b = 4 * j + bg;
                int pidx = kc * 272 + b * 17 + r;
                pb0[pidx] = lo_f(acc0[i * 4 + j]) + hi_f(acc0[i * 4 + j]);
                pb1[pidx] = lo_f(acc1[i * 4 + j]) + hi_f(acc1[i * 4 + j]);
            }
        }
        __syncthreads();

        // ---- reduce across 16 k-chunks
        float g0 = x0v, g1 = biasr;
        {
            int base = rb * 17 + row;
            #pragma unroll
            for (int k = 0; k < 16; ++k) {
                g0 += pb0[k * 272 + base];
                g1 += pb1[k * 272 + base];
            }
        }

        // ---- gather gates via shuffles
        float f0 = __shfl_down_sync(0xffffffffu, g0, 4);
        float gg0 = __shfl_down_sync(0xffffffffu, g0, 8);
        float o0 = __shfl_down_sync(0xffffffffu, g0, 12);
        float i1 = __shfl_up_sync(0xffffffffu, g1, 8);
        float f1 = __shfl_up_sync(0xffffffffu, g1, 4);
        float o1 = __shfl_down_sync(0xffffffffu, g1, 4);

        // ---- cell 0 (step t), lanes row<4, register state
        if (t < TT && isC0) {
            float iv = expf(g0);
            float fv = 1.f / (1.f + expf(-f0));
            float gv = tanhf(gg0);
            float ov = 1.f / (1.f + expf(-o0));
            n0r = fmaf(fv, n0r, iv);
            c0r = fmaf(fv, c0r, iv * gv);
            h0fin = ov * (c0r / (n0r + 1e-8f));
            g_h0[t & 1][hidx0] = h0fin;
        }
        // ---- cell 1 (step t-1), lanes 8<=row<12, register state
        if (t >= 1 && isC1) {
            float iv = expf(i1);
            float fv = 1.f / (1.f + expf(-f1));
            float gv = tanhf(g1);
            float ov = 1.f / (1.f + expf(-o1));
            n1r = fmaf(fv, n1r, iv);
            c1r = fmaf(fv, c1r, iv * gv);
            h1fin = ov * (c1r / (n1r + 1e-8f));
            g_h1[(t - 1) & 1][hidx1] = h1fin;
            out[(size_t)(t - 1) * BH + hidx1] = h1fin;
        }
        __syncthreads();
        if (tid == 0) cta_arrive(ctr);
    }

    // ---- final states: hn[2,B,H], cn[2,B,H], nn[2,B,H]
    size_t base = (size_t)TT * BH;
    if (isC0) {
        out[base + 0 * BH + hidx0] = h0fin;
        out[base + 2 * BH + hidx0] = c0r;
        out[base + 4 * BH + hidx0] = n0r;
    }
    if (isC1) {
        out[base + 1 * BH + hidx1] = h1fin;
        out[base + 3 * BH + hidx1] = c1r;
        out[base + 5 * BH + hidx1] = n1r;
    }
}

extern "C" void kernel_launch(void* const* d_in, const int* in_sizes, int n_in,
                              void* d_out, int out_size) {
    (void)in_sizes; (void)n_in; (void)out_size;
    const float* input  = (const float*)d_in[0];
    const float* w_ih0  = (const float*)d_in[1];
    const float* w_hh0  = (const float*)d_in[2];
    const float* b0     = (const float*)d_in[3];
    const float* w_ih1  = (const float*)d_in[4];
    const float* w_hh1  = (const float*)d_in[5];
    const float* b1     = (const float*)d_in[6];
    float* out = (float*)d_out;

    int smem_bytes = SM_TOT * 4;   // 198656 B
    cudaFuncSetAttribute(slstm_kernel, cudaFuncAttributeMaxDynamicSharedMemorySize, smem_bytes);

    x0_gemm_kernel<<<dim3(G4 / 64, (TT * BATCH) / 64), 256>>>(input, w_ih0, b0);
    slstm_kernel<<<NCTA, NTH, smem_bytes>>>(w_hh0, w_ih1, w_hh1, b1, out);
}

// round 7
// speedup vs baseline: 1.4806x; 1.3146x over previous
#include <cuda_runtime.h>
#include <math.h>

#define TT    2048
#define BATCH 16
#define HD    512
#define G4    2048
#define NCTA  128
#define NTH   256
#define BH    (BATCH * HD)

typedef unsigned long long u64;

__device__ __forceinline__ u64 fma2(u64 a, u64 b, u64 c) {
    u64 d;
    asm("fma.rn.f32x2 %0, %1, %2, %3;" : "=l"(d) : "l"(a), "l"(b), "l"(c));
    return d;
}
__device__ __forceinline__ u64 pk2(float a, float b) {
    u64 d;
    asm("mov.b64 %0, {%1, %2};" : "=l"(d) : "f"(a), "f"(b));
    return d;
}
__device__ __forceinline__ float lo_f(u64 v) { return __uint_as_float((unsigned)v); }
__device__ __forceinline__ float hi_f(u64 v) { return __uint_as_float((unsigned)(v >> 32)); }

__device__ __forceinline__ unsigned f2tf32(float a) {
    unsigned r;
    asm("cvt.rna.tf32.f32 %0, %1;" : "=r"(r) : "f"(a));
    return r;
}
__device__ __forceinline__ unsigned short bf16r(float x) {
    unsigned u = __float_as_uint(x);
    unsigned r = (u + 0x7fffu + ((u >> 16) & 1u)) >> 16;
    return (unsigned short)r;
}
__device__ __forceinline__ void mma8(float* c, unsigned a0, unsigned a1,
                                     unsigned a2, unsigned a3,
                                     unsigned b0, unsigned b1) {
    asm volatile(
        "mma.sync.aligned.m16n8k8.row.col.f32.tf32.tf32.f32 "
        "{%0,%1,%2,%3}, {%4,%5,%6,%7}, {%8,%9}, {%0,%1,%2,%3};"
        : "+f"(c[0]), "+f"(c[1]), "+f"(c[2]), "+f"(c[3])
        : "r"(a0), "r"(a1), "r"(a2), "r"(a3), "r"(b0), "r"(b1));
}

// Scratch (__device__ globals per allocation-free rules)
__device__ float g_x0[(size_t)TT * NCTA * 256];   // [t][cta][b][16 rows]
__device__ float g_h0[2][BH];
__device__ float g_h1[2][BH];
__device__ unsigned g_ctr[32];

__device__ __forceinline__ void cta_arrive(unsigned* p) {
    asm volatile("red.release.gpu.add.u32 [%0], %1;" :: "l"(p), "r"(1u) : "memory");
}
__device__ __forceinline__ void cta_spin(unsigned* p, unsigned tgt) {
    unsigned v;
    do {
        asm volatile("ld.acquire.gpu.u32 %0, [%1];" : "=r"(v) : "l"(p) : "memory");
    } while (v < tgt);
}

// ---------------------------------------------------------------------------
// X0 GEMM (+ scratch init in block (0,0)): packed-j f32x2 FMAs.
// ---------------------------------------------------------------------------
__global__ void __launch_bounds__(256) x0_gemm_kernel(
    const float* __restrict__ A, const float* __restrict__ W,
    const float* __restrict__ bias)
{
    if (blockIdx.x == 0 && blockIdx.y == 0) {
        for (int i = threadIdx.x; i < 32; i += 256) g_ctr[i] = 0u;
        for (int i = threadIdx.x; i < BH; i += 256) {
            g_h0[0][i] = 0.f; g_h0[1][i] = 0.f;
            g_h1[0][i] = 0.f; g_h1[1][i] = 0.f;
        }
    }

    __shared__ float As[16][68];
    __shared__ float Ws[16][68];
    int tid = threadIdx.x;
    int tx = tid & 15, ty = tid >> 4;
    int m0 = blockIdx.y * 64, n0 = blockIdx.x * 64;
    int lr = tid >> 2;
    int lc = (tid & 3) << 2;
    u64 acc2[4][2] = {};
    for (int k0 = 0; k0 < 512; k0 += 16) {
        float4 av = *(const float4*)&A[(size_t)(m0 + lr) * 512 + k0 + lc];
        float4 wv = *(const float4*)&W[(size_t)(n0 + lr) * 512 + k0 + lc];
        As[lc + 0][lr] = av.x; As[lc + 1][lr] = av.y;
        As[lc + 2][lr] = av.z; As[lc + 3][lr] = av.w;
        Ws[lc + 0][lr] = wv.x; Ws[lc + 1][lr] = wv.y;
        Ws[lc + 2][lr] = wv.z; Ws[lc + 3][lr] = wv.w;
        __syncthreads();
        #pragma unroll
        for (int k = 0; k < 16; ++k) {
            float4 a4 = *(const float4*)&As[k][ty * 4];
            ulonglong2 w2 = *(const ulonglong2*)&Ws[k][tx * 4];
            u64 pa0 = pk2(a4.x, a4.x);
            u64 pa1 = pk2(a4.y, a4.y);
            u64 pa2 = pk2(a4.z, a4.z);
            u64 pa3 = pk2(a4.w, a4.w);
            acc2[0][0] = fma2(pa0, w2.x, acc2[0][0]);
            acc2[0][1] = fma2(pa0, w2.y, acc2[0][1]);
            acc2[1][0] = fma2(pa1, w2.x, acc2[1][0]);
            acc2[1][1] = fma2(pa1, w2.y, acc2[1][1]);
            acc2[2][0] = fma2(pa2, w2.x, acc2[2][0]);
            acc2[2][1] = fma2(pa2, w2.y, acc2[2][1]);
            acc2[3][0] = fma2(pa3, w2.x, acc2[3][0]);
            acc2[3][1] = fma2(pa3, w2.y, acc2[3][1]);
        }
        __syncthreads();
    }
    float4 bv = *(const float4*)&bias[n0 + tx * 4];
    int n = n0 + tx * 4;
    int g = n >> 9;
    int cta = (n >> 2) & 127;
    #pragma unroll
    for (int i = 0; i < 4; ++i) {
        int m = m0 + ty * 4 + i;
        int t = m >> 4, b = m & 15;
        float4 r;
        r.x = lo_f(acc2[i][0]) + bv.x; r.y = hi_f(acc2[i][0]) + bv.y;
        r.z = lo_f(acc2[i][1]) + bv.z; r.w = hi_f(acc2[i][1]) + bv.w;
        size_t dst = (((size_t)t * NCTA + cta) * 16 + b) * 16 + g * 4;
        *(float4*)&g_x0[dst] = r;
    }
}

// ---------------------------------------------------------------------------
// Persistent recurrent kernel: tf32 tensor-core MMA (error-compensated).
// Per CTA: gates[16 rows x 16 batch], K=512 split across 8 warps (8 k8-tiles).
// Weights as pre-built A-fragments in smem (tf32 hi + bf16-packed lo).
// h reloaded per step into warp-private B-fragment smem.
// ---------------------------------------------------------------------------
// smem byte offsets
#define OFF_WAHI 0                 // 3 * 8192 u32  = 98304 B
#define OFF_WALO 98304             // 3 * 8192 u16  = 49152 B
#define OFF_HB0  147456            // 8192 f32      = 32768 B
#define OFF_HB1  180224            // 8192 f32      = 32768 B
#define OFF_PB   212992            // 4096 f32      = 16384 B
#define SMEM_BYTES 229376

__global__ void __launch_bounds__(NTH, 1) slstm_kernel(
    const float* __restrict__ w_hh0,
    const float* __restrict__ w_ih1,
    const float* __restrict__ w_hh1,
    const float* __restrict__ b1,
    float* __restrict__ out)
{
    extern __shared__ char smc[];
    unsigned*       WAHI = (unsigned*)(smc + OFF_WAHI);
    unsigned short* WALO = (unsigned short*)(smc + OFF_WALO);
    float*          HB0f = (float*)(smc + OFF_HB0);
    float*          HB1f = (float*)(smc + OFF_HB1);
    float*          PB   = (float*)(smc + OFF_PB);

    const int cta  = blockIdx.x;
    const int tid  = threadIdx.x;
    const int lane = tid & 31;
    const int w    = tid >> 5;
    const int g    = lane >> 2;    // fragment groupID
    const int tg   = lane & 3;     // fragment threadID_in_group

    // ---- build weight A-fragments in smem (once) ----
    #pragma unroll 1
    for (int m = 0; m < 3; ++m) {
        const float* Wsrc = (m == 0) ? w_hh0 : (m == 1) ? w_ih1 : w_hh1;
        for (int idx = tid; idx < 8192; idx += NTH) {
            int kt = idx >> 7, rem = idx & 127;
            int l = rem >> 2, j = rem & 3;
            int gg = l >> 2, tt = l & 3;
            int row = gg + (j & 1) * 8;
            int k = kt * 8 + tt + (j >> 1) * 4;
            int grow = (row >> 2) * HD + cta * 4 + (row & 3);
            float a = __ldg(&Wsrc[(size_t)grow * 512 + k]);
            unsigned ah = f2tf32(a);
            float alf = a - __uint_as_float(ah);
            WAHI[m * 8192 + idx] = ah;
            WALO[m * 8192 + idx] = bf16r(alf);
        }
    }
    __syncthreads();

    // reduce / cell mapping
    const int b   = tid >> 4;      // batch
    const int r   = tid & 15;      // gate row
    const bool isC0 = (r < 4);
    const bool isC1 = (r >= 8 && r < 12);
    const int hidx0 = b * HD + cta * 4 + r;
    const int hidx1 = b * HD + cta * 4 + (r - 8);
    const float biasr = b1[(r >> 2) * HD + cta * 4 + (r & 3)];
    float c0r = 0.f, n0r = 0.f, h0fin = 0.f;
    float c1r = 0.f, n1r = 0.f, h1fin = 0.f;

    unsigned* ctr = &g_ctr[0];
    const int k4w  = 16 * w + (lane & 15);     // reload f4 column
    const int rkt  = k4w >> 1, rslot = k4w & 1;
    const int pbo  = r * 16 + ((b + r) & 15);  // reduce read offset

    for (int t = 0; t <= TT; ++t) {
        // x0 prefetch (independent of spin)
        float x0v = 0.f;
        if (t < TT) x0v = __ldcg(&g_x0[(((size_t)t * NCTA + cta) << 8) + tid]);

        // ---- spin: all CTAs finished slot t-1 ----
        if (t > 0) {
            if (lane == 0) cta_spin(ctr, 128u * (unsigned)t);
            __syncwarp();
        }

        // ---- warp-local reload of h0(t-1), h1(t-2) into B-frag layout ----
        {
            const float4* s0 = (const float4*)g_h0[(t + 1) & 1];
            const float4* s1 = (const float4*)g_h1[t & 1];
            #pragma unroll
            for (int i = 0; i < 8; ++i) {
                int bb = (lane >> 4) + 2 * i;
                float4 v0 = __ldcg(s0 + bb * 128 + k4w);
                float4 v1 = __ldcg(s1 + bb * 128 + k4w);
                int addr = (rkt * 2 + (bb >> 3)) * 64 + rslot * 32
                         + (((bb & 7) + 2 * rkt + rslot) & 7) * 4;
                *(float4*)(HB0f + addr) = v0;
                *(float4*)(HB1f + addr) = v1;
            }
            __syncwarp();
        }

        // ---- tensor GEMM over this warp's 8 k8-tiles ----
        float acc[4][4];
        #pragma unroll
        for (int s = 0; s < 4; ++s)
            #pragma unroll
            for (int q = 0; q < 4; ++q) acc[s][q] = 0.f;

        #pragma unroll 4
        for (int j = 0; j < 8; ++j) {
            int kt = 8 * w + j;
            const unsigned* wa = WAHI + kt * 128 + lane * 4;
            uint4 a0h = *(const uint4*)(wa);
            uint4 aih = *(const uint4*)(wa + 8192);
            uint4 ahh = *(const uint4*)(wa + 16384);
            const unsigned short* wl = WALO + kt * 128 + lane * 4;
            ushort4 l0 = *(const ushort4*)(wl);
            ushort4 li = *(const ushort4*)(wl + 8192);
            ushort4 lh = *(const ushort4*)(wl + 16384);
            unsigned a0l0 = ((unsigned)l0.x) << 16, a0l1 = ((unsigned)l0.y) << 16;
            unsigned a0l2 = ((unsigned)l0.z) << 16, a0l3 = ((unsigned)l0.w) << 16;
            unsigned ail0 = ((unsigned)li.x) << 16, ail1 = ((unsigned)li.y) << 16;
            unsigned ail2 = ((unsigned)li.z) << 16, ail3 = ((unsigned)li.w) << 16;
            unsigned ahl0 = ((unsigned)lh.x) << 16, ahl1 = ((unsigned)lh.y) << 16;
            unsigned ahl2 = ((unsigned)lh.z) << 16, ahl3 = ((unsigned)lh.w) << 16;

            #pragma unroll
            for (int nt = 0; nt < 2; ++nt) {
                int base = (kt * 2 + nt) * 64;
                int o0 = base + ((g + 2 * kt) & 7) * 4 + tg;
                int o1 = base + 32 + ((g + 2 * kt + 1) & 7) * 4 + tg;
                float p0 = HB0f[o0], p1 = HB0f[o1];
                float q0 = HB1f[o0], q1 = HB1f[o1];
                unsigned p0h = f2tf32(p0), p1h = f2tf32(p1);
                unsigned q0h = f2tf32(q0), q1h = f2tf32(q1);
                unsigned p0l = f2tf32(p0 - __uint_as_float(p0h));
                unsigned p1l = f2tf32(p1 - __uint_as_float(p1h));
                unsigned q0l = f2tf32(q0 - __uint_as_float(q0h));
                unsigned q1l = f2tf32(q1 - __uint_as_float(q1h));

                // L0: W0 @ h0
                mma8(acc[nt], a0h.x, a0h.y, a0h.z, a0h.w, p0h, p1h);
                mma8(acc[nt], a0h.x, a0h.y, a0h.z, a0h.w, p0l, p1l);
                mma8(acc[nt], a0l0, a0l1, a0l2, a0l3, p0h, p1h);
                // L1: W1I @ h0
                mma8(acc[2 + nt], aih.x, aih.y, aih.z, aih.w, p0h, p1h);
                mma8(acc[2 + nt], aih.x, aih.y, aih.z, aih.w, p0l, p1l);
                mma8(acc[2 + nt], ail0, ail1, ail2, ail3, p0h, p1h);
                // L1: W1H @ h1
                mma8(acc[2 + nt], ahh.x, ahh.y, ahh.z, ahh.w, q0h, q1h);
                mma8(acc[2 + nt], ahh.x, ahh.y, ahh.z, ahh.w, q0l, q1l);
                mma8(acc[2 + nt], ahl0, ahl1, ahl2, ahl3, q0h, q1h);
            }
        }

        // ---- store partials ----
        #pragma unroll
        for (int L = 0; L < 2; ++L)
            #pragma unroll
            for (int nt = 0; nt < 2; ++nt) {
                float* c = acc[L * 2 + nt];
                int col = nt * 8 + 2 * tg;
                int bi = w * 512 + L * 256;
                PB[bi + g * 16 + ((col + g) & 15)]           = c[0];
                PB[bi + g * 16 + ((col + 1 + g) & 15)]       = c[1];
                PB[bi + (g + 8) * 16 + ((col + g + 8) & 15)]     = c[2];
                PB[bi + (g + 8) * 16 + ((col + 1 + g + 8) & 15)] = c[3];
            }
        __syncthreads();

        // ---- reduce across 8 warps ----
        float g0 = x0v, g1 = biasr;
        #pragma unroll
        for (int w8 = 0; w8 < 8; ++w8) {
            g0 += PB[w8 * 512 + pbo];
            g1 += PB[w8 * 512 + 256 + pbo];
        }

        // ---- gather gates via shuffles (lane = (b&1)*16 + r) ----
        float f0  = __shfl_down_sync(0xffffffffu, g0, 4);
        float gg0 = __shfl_down_sync(0xffffffffu, g0, 8);
        float o0  = __shfl_down_sync(0xffffffffu, g0, 12);
        float i1  = __shfl_up_sync(0xffffffffu, g1, 8);
        float f1  = __shfl_up_sync(0xffffffffu, g1, 4);
        float o1  = __shfl_down_sync(0xffffffffu, g1, 4);

        // ---- cell 0 (step t), threads r<4 ----
        if (t < TT && isC0) {
            float iv = expf(g0);
            float fv = 1.f / (1.f + expf(-f0));
            float gv = tanhf(gg0);
            float ov = 1.f / (1.f + expf(-o0));
            n0r = fmaf(fv, n0r, iv);
            c0r = fmaf(fv, c0r, iv * gv);
            h0fin = ov * (c0r / (n0r + 1e-8f));
            g_h0[t & 1][hidx0] = h0fin;
            __threadfence();
        }
        // ---- cell 1 (step t-1), threads 8<=r<12 ----
        if (t >= 1 && isC1) {
            float iv = expf(i1);
            float fv = 1.f / (1.f + expf(-f1));
            float gv = tanhf(g1);
            float ov = 1.f / (1.f + expf(-o1));
            n1r = fmaf(fv, n1r, iv);
            c1r = fmaf(fv, c1r, iv * gv);
            h1fin = ov * (c1r / (n1r + 1e-8f));
            g_h1[(t - 1) & 1][hidx1] = h1fin;
            out[(size_t)(t - 1) * BH + hidx1] = h1fin;
            __threadfence();
        }
        __syncthreads();
        if (tid == 0) cta_arrive(ctr);
    }

    // ---- final states: hn[2,B,H], cn[2,B,H], nn[2,B,H] ----
    size_t base = (size_t)TT * BH;
    if (isC0) {
        out[base + 0 * BH + hidx0] = h0fin;
        out[base + 2 * BH + hidx0] = c0r;
        out[base + 4 * BH + hidx0] = n0r;
    }
    if (isC1) {
        out[base + 1 * BH + hidx1] = h1fin;
        out[base + 3 * BH + hidx1] = c1r;
        out[base + 5 * BH + hidx1] = n1r;
    }
}

extern "C" void kernel_launch(void* const* d_in, const int* in_sizes, int n_in,
                              void* d_out, int out_size) {
    (void)in_sizes; (void)n_in; (void)out_size;
    const float* input  = (const float*)d_in[0];
    const float* w_ih0  = (const float*)d_in[1];
    const float* w_hh0  = (const float*)d_in[2];
    const float* b0     = (const float*)d_in[3];
    const float* w_ih1  = (const float*)d_in[4];
    const float* w_hh1  = (const float*)d_in[5];
    const float* b1     = (const float*)d_in[6];
    float* out = (float*)d_out;

    cudaFuncSetAttribute(slstm_kernel, cudaFuncAttributeMaxDynamicSharedMemorySize,
                         SMEM_BYTES);

    x0_gemm_kernel<<<dim3(G4 / 64, (TT * BATCH) / 64), 256>>>(input, w_ih0, b0);
    slstm_kernel<<<NCTA, NTH, SMEM_BYTES>>>(w_hh0, w_ih1, w_hh1, b1, out);
}